// round 1
// baseline (speedup 1.0000x reference)
#include <cuda_runtime.h>

// Wealth_21182778704643 — GB300 sm_103a
// out[b] = DT * sum_t( dot(action[b,t,:], mu[b,:,t]) + bt[t] )
//        - (GAMMA/2)*DT * sum_{t,m} ( sum_n action[b,t,n]*sigma[b,t,n,m] + zeta[b,t,m] )^2
//
// HBM-bound: sigma is 536.9 MB, read once. Strategy: perfectly-coalesced
// float4 streaming of sigma, smem-staged action/mu tiles, per-(b,t) shuffle
// reduction, one float atomicAdd per (b,t) into out[b].

#define B_DIM 64
#define T_DIM 512
#define N_DIM 64
#define M_DIM 64

#define TB 32            // time steps per block
#define THREADS 512      // 16 threads per time step (each owns 4 m-columns)
#define MU_PAD (TB + 1)  // pad to 33 to avoid smem bank conflicts

__device__ __forceinline__ float k_dt()    { return 1.0f / 252.0f; }
__device__ __forceinline__ float k_pen()   { return 0.5f * 0.1f * (1.0f / 252.0f); } // GAMMA/2*DT

__global__ void wealth_zero_kernel(float* __restrict__ out) {
    if (threadIdx.x < B_DIM) out[threadIdx.x] = 0.0f;
}

__global__ __launch_bounds__(THREADS, 2)
void wealth_main_kernel(const float* __restrict__ action,
                        const float* __restrict__ mu,
                        const float* __restrict__ sigma,
                        const float* __restrict__ zeta,
                        const float* __restrict__ bt,
                        float* __restrict__ out)
{
    __shared__ float a_s[TB * N_DIM];        // action[b, t0:t0+TB, :]   8 KB
    __shared__ float mu_s[N_DIM * MU_PAD];   // mu[b, :, t0:t0+TB] padded 8.25 KB

    const int b   = blockIdx.y;
    const int t0  = blockIdx.x * TB;
    const int tid = threadIdx.x;

    // --- Stage action tile (contiguous 8 KB, coalesced) ---
    const float* ap = action + ((size_t)b * T_DIM + t0) * N_DIM;
    #pragma unroll
    for (int i = tid; i < TB * N_DIM; i += THREADS) a_s[i] = ap[i];

    // --- Stage mu tile: mu[b, n, t0+tl], 32 consecutive t's per n (coalesced 128B) ---
    const float* mp = mu + (size_t)b * N_DIM * T_DIM + t0;
    #pragma unroll
    for (int i = tid; i < N_DIM * TB; i += THREADS) {
        int n  = i >> 5;      // i / 32
        int tl = i & 31;      // i % 32
        mu_s[n * MU_PAD + tl] = mp[(size_t)n * T_DIM + tl];
    }
    __syncthreads();

    const int g = tid >> 4;   // local time step 0..31
    const int q = tid & 15;   // float4 column group 0..15 (covers m = 4q..4q+3)
    const int t = t0 + g;

    // --- Stream sigma[b, t, :, :] as float4 (fully coalesced, 64 independent LDG.128) ---
    const float4* sig4 = (const float4*)(sigma + (((size_t)b * T_DIM + t) * N_DIM) * M_DIM);
    const float*  ag   = a_s + g * N_DIM;

    float4 acc = make_float4(0.f, 0.f, 0.f, 0.f);
    #pragma unroll
    for (int n = 0; n < N_DIM; ++n) {
        const float  an = ag[n];                // smem broadcast within group
        const float4 s  = sig4[n * (M_DIM / 4) + q];
        acc.x = fmaf(an, s.x, acc.x);
        acc.y = fmaf(an, s.y, acc.y);
        acc.z = fmaf(an, s.z, acc.z);
        acc.w = fmaf(an, s.w, acc.w);
    }

    // --- (risk + zeta)^2, partial sum over this thread's 4 m's ---
    const float4 z = ((const float4*)(zeta + ((size_t)b * T_DIM + t) * M_DIM))[q];
    const float vx = acc.x + z.x;
    const float vy = acc.y + z.y;
    const float vz = acc.z + z.z;
    const float vw = acc.w + z.w;
    float sq = vx * vx + vy * vy + vz * vz + vw * vw;

    // --- wealth dot partial: n = 4q .. 4q+3 ---
    float wp = 0.f;
    #pragma unroll
    for (int j = 0; j < 4; ++j) {
        const int n = q * 4 + j;
        wp = fmaf(ag[n], mu_s[n * MU_PAD + g], wp);
    }

    // --- reduce within the 16-thread group (lanes 0-15 / 16-31 of a warp) ---
    #pragma unroll
    for (int off = 8; off; off >>= 1) {
        sq += __shfl_xor_sync(0xffffffffu, sq, off, 16);
        wp += __shfl_xor_sync(0xffffffffu, wp, off, 16);
    }

    if (q == 0) {
        const float rw      = wp + bt[t];
        const float contrib = k_dt() * rw - k_pen() * sq;
        atomicAdd(out + b, contrib);
    }
}

extern "C" void kernel_launch(void* const* d_in, const int* in_sizes, int n_in,
                              void* d_out, int out_size)
{
    const float* action = (const float*)d_in[0];  // (B, T, N)
    const float* mu     = (const float*)d_in[1];  // (B, N, T)
    const float* sigma  = (const float*)d_in[2];  // (B, T, N, M)
    const float* zeta   = (const float*)d_in[3];  // (B, T, M)
    const float* bt     = (const float*)d_in[4];  // (T, 1)
    float* out          = (float*)d_out;          // (B,)

    (void)in_sizes; (void)n_in; (void)out_size;

    wealth_zero_kernel<<<1, 64>>>(out);
    dim3 grid(T_DIM / TB, B_DIM);
    wealth_main_kernel<<<grid, THREADS>>>(action, mu, sigma, zeta, bt, out);
}

// round 2
// speedup vs baseline: 1.0572x; 1.0572x over previous
#include <cuda_runtime.h>

// Wealth_21182778704643 — GB300 sm_103a, R2
// HBM-streaming bound (sigma = 537 MB read once). R1 hit 91.7us at DRAM=80.1%;
// loss was wave quantization (3.46 -> 4 waves). R2 halves the per-block tile
// (TB=16, one warp per time step, each lane owns 32 sigma LDG.128) so the grid
// is 2048 blocks -> 6.92 -> 7 waves, tail waste 15.6% -> 1.2%.

#define B_DIM 64
#define T_DIM 512
#define N_DIM 64
#define M_DIM 64

#define TB 16            // time steps per block (one warp each)
#define THREADS 512
#define MU_PAD 17        // pad mu tile rows to kill bank conflicts

__device__ __forceinline__ float k_dt()  { return 1.0f / 252.0f; }
__device__ __forceinline__ float k_pen() { return 0.5f * 0.1f * (1.0f / 252.0f); } // GAMMA/2*DT

__global__ void wealth_zero_kernel(float* __restrict__ out) {
    if (threadIdx.x < B_DIM) out[threadIdx.x] = 0.0f;
}

__global__ __launch_bounds__(THREADS, 2)
void wealth_main_kernel(const float* __restrict__ action,
                        const float* __restrict__ mu,
                        const float* __restrict__ sigma,
                        const float* __restrict__ zeta,
                        const float* __restrict__ bt,
                        float* __restrict__ out)
{
    __shared__ float a_s[TB * N_DIM];        // action[b, t0:t0+TB, :]   4 KB
    __shared__ float mu_s[N_DIM * MU_PAD];   // mu[b, :, t0:t0+TB] padded

    const int b   = blockIdx.y;
    const int t0  = blockIdx.x * TB;
    const int tid = threadIdx.x;

    // --- Stage action tile (contiguous 4 KB, coalesced) ---
    const float* ap = action + ((size_t)b * T_DIM + t0) * N_DIM;
    #pragma unroll
    for (int i = tid; i < TB * N_DIM; i += THREADS) a_s[i] = ap[i];

    // --- Stage mu tile: mu[b, n, t0+tl] (16 consecutive t per n, 64B segs) ---
    const float* mp = mu + (size_t)b * N_DIM * T_DIM + t0;
    #pragma unroll
    for (int i = tid; i < N_DIM * TB; i += THREADS) {
        int n  = i >> 4;      // i / 16
        int tl = i & 15;      // i % 16
        mu_s[n * MU_PAD + tl] = mp[(size_t)n * T_DIM + tl];
    }
    __syncthreads();

    const int w    = tid >> 5;     // warp id = local time step 0..15
    const int lane = tid & 31;
    const int q    = lane & 15;    // m float4 group 0..15
    const int h    = lane >> 4;    // n half: 0 -> n 0..31, 1 -> n 32..63
    const int t    = t0 + w;

    // --- Stream sigma[b, t, h*32 + n', 4q..4q+3], n' = 0..31 ---
    // Warp footprint per iteration: 2 rows x 256B = 4 full 128B lines.
    const float4* sig4 = (const float4*)(sigma + (((size_t)b * T_DIM + t) * N_DIM) * M_DIM)
                         + (size_t)h * 32 * (M_DIM / 4) + q;
    const float*  ag   = a_s + w * N_DIM + h * 32;

    float4 acc = make_float4(0.f, 0.f, 0.f, 0.f);
    #pragma unroll
    for (int n = 0; n < 32; ++n) {
        const float  an = ag[n];
        const float4 s  = sig4[n * (M_DIM / 4)];
        acc.x = fmaf(an, s.x, acc.x);
        acc.y = fmaf(an, s.y, acc.y);
        acc.z = fmaf(an, s.z, acc.z);
        acc.w = fmaf(an, s.w, acc.w);
    }

    // --- combine the two n-halves (acc must be complete before squaring) ---
    acc.x += __shfl_xor_sync(0xffffffffu, acc.x, 16);
    acc.y += __shfl_xor_sync(0xffffffffu, acc.y, 16);
    acc.z += __shfl_xor_sync(0xffffffffu, acc.z, 16);
    acc.w += __shfl_xor_sync(0xffffffffu, acc.w, 16);

    // --- (risk + zeta)^2 partial for this m-quad ---
    const float4 z = ((const float4*)(zeta + ((size_t)b * T_DIM + t) * M_DIM))[q];
    const float vx = acc.x + z.x;
    const float vy = acc.y + z.y;
    const float vz = acc.z + z.z;
    const float vw = acc.w + z.w;
    float sq = vx * vx + vy * vy + vz * vz + vw * vw;

    // reduce sq over the 16 m-quads (both halves hold identical totals)
    #pragma unroll
    for (int off = 8; off; off >>= 1)
        sq += __shfl_xor_sync(0xffffffffu, sq, off, 16);

    // --- wealth dot partial: each lane covers n = h*32 + 2q, 2q+1 ---
    const int n0 = h * 32 + q * 2;
    float wp = fmaf(a_s[w * N_DIM + n0],     mu_s[n0 * MU_PAD + w],
               a_s[w * N_DIM + n0 + 1] * mu_s[(n0 + 1) * MU_PAD + w]);
    #pragma unroll
    for (int off = 16; off; off >>= 1)
        wp += __shfl_xor_sync(0xffffffffu, wp, off);

    if (lane == 0) {
        const float rw      = wp + bt[t];
        const float contrib = k_dt() * rw - k_pen() * sq;
        atomicAdd(out + b, contrib);
    }
}

extern "C" void kernel_launch(void* const* d_in, const int* in_sizes, int n_in,
                              void* d_out, int out_size)
{
    const float* action = (const float*)d_in[0];  // (B, T, N)
    const float* mu     = (const float*)d_in[1];  // (B, N, T)
    const float* sigma  = (const float*)d_in[2];  // (B, T, N, M)
    const float* zeta   = (const float*)d_in[3];  // (B, T, M)
    const float* bt     = (const float*)d_in[4];  // (T, 1)
    float* out          = (float*)d_out;          // (B,)

    (void)in_sizes; (void)n_in; (void)out_size;

    wealth_zero_kernel<<<1, 64>>>(out);
    dim3 grid(T_DIM / TB, B_DIM);
    wealth_main_kernel<<<grid, THREADS>>>(action, mu, sigma, zeta, bt, out);
}